// round 1
// baseline (speedup 1.0000x reference)
#include <cuda_runtime.h>
#include <cstdint>

#define NTHREADS 256
#define KTOP 30
#define CCOLS 32000
#define NF4 (CCOLS / 4)     // 8000 float4 per row
#define CAP 2048
#define MAXB 4096

// Per-row weighted loss scratch (device global: no allocation allowed).
__device__ float g_rowloss[MAXB];

__device__ __forceinline__ unsigned ordu(float f) {
    unsigned u = __float_as_uint(f);
    return (u & 0x80000000u) ? ~u : (u | 0x80000000u);
}
// 64-bit key: value (order-preserving) in high bits, ~index low.
// For equal values, smaller index => larger key (matches jax top_k tie-break).
__device__ __forceinline__ unsigned long long mkkey(float f, unsigned idx) {
    return (((unsigned long long)ordu(f)) << 32) | (unsigned long long)(~idx);
}

struct SMem {
    unsigned long long buf[CAP];
    unsigned long long wred[8];
    float gmax[64];
    int   tIdx[KTOP];
    int   cnt;
    int   ov;
    float loss;
};

// Exact top-30 (by key) of one row of CCOLS floats.
// On return (all threads synced): s->buf[0..29] = top-30 keys, descending.
__device__ void topk_select(const float4* __restrict__ row4, SMem* s) {
    const int tid = threadIdx.x;
    if (tid == 0) s->cnt = 0;

    // ---- Pass A: per-thread max over bootstrap chunk (first 8192 elems) ----
    float m = -3.402823466e38f;
#pragma unroll
    for (int k = 0; k < 8; k++) {
        float4 v = __ldg(&row4[tid + (k << 8)]);
        m = fmaxf(m, fmaxf(fmaxf(v.x, v.y), fmaxf(v.z, v.w)));
    }
    // group of 4 lanes -> 64 group maxes
    m = fmaxf(m, __shfl_xor_sync(0xFFFFFFFFu, m, 1));
    m = fmaxf(m, __shfl_xor_sync(0xFFFFFFFFu, m, 2));
    if ((tid & 3) == 0) s->gmax[tid >> 2] = m;
    __syncthreads();

    // bitonic sort 64 floats, descending (threads 0..63 active, all sync)
    for (int k = 2; k <= 64; k <<= 1) {
        for (int j = k >> 1; j > 0; j >>= 1) {
            if (tid < 64) {
                int l = tid ^ j;
                if (l > tid) {
                    float a = s->gmax[tid], b = s->gmax[l];
                    if ((a < b) == ((tid & k) == 0)) {
                        s->gmax[tid] = b;
                        s->gmax[l] = a;
                    }
                }
            }
            __syncthreads();
        }
    }
    const float th = s->gmax[KTOP - 1];   // safe threshold: th <= 30th-largest elem

    // ---- Pass B: full scan, push candidates >= th ----
    const float qnan = __int_as_float(0x7fc00000);
    for (int base = 0; base < NF4; base += NTHREADS * 8) {
        float4 w[8];
#pragma unroll
        for (int k = 0; k < 8; k++) {
            int j4 = base + (k << 8) + tid;
            w[k] = (j4 < NF4) ? __ldg(&row4[j4])
                              : make_float4(qnan, qnan, qnan, qnan);
        }
#pragma unroll
        for (int k = 0; k < 8; k++) {
            int j4 = base + (k << 8) + tid;
            unsigned e = (unsigned)(j4 << 2);
            float4 v = w[k];
            if (v.x >= th) { int p = atomicAdd(&s->cnt, 1); if (p < CAP) s->buf[p] = mkkey(v.x, e); }
            if (v.y >= th) { int p = atomicAdd(&s->cnt, 1); if (p < CAP) s->buf[p] = mkkey(v.y, e + 1); }
            if (v.z >= th) { int p = atomicAdd(&s->cnt, 1); if (p < CAP) s->buf[p] = mkkey(v.z, e + 2); }
            if (v.w >= th) { int p = atomicAdd(&s->cnt, 1); if (p < CAP) s->buf[p] = mkkey(v.w, e + 3); }
        }
    }
    __syncthreads();
    int cnt = s->cnt;

    // ---- Fallback (statistically never taken): exact 30x argmax extraction ----
    if (cnt > CAP) {
        unsigned long long prev = 0xFFFFFFFFFFFFFFFFull;
        for (int r = 0; r < KTOP; r++) {
            unsigned long long best = 0ull;
            for (int j4 = tid; j4 < NF4; j4 += NTHREADS) {
                float4 v = __ldg(&row4[j4]);
                unsigned e = (unsigned)(j4 << 2);
                unsigned long long kk;
                kk = mkkey(v.x, e);     if (kk < prev && kk > best) best = kk;
                kk = mkkey(v.y, e + 1); if (kk < prev && kk > best) best = kk;
                kk = mkkey(v.z, e + 2); if (kk < prev && kk > best) best = kk;
                kk = mkkey(v.w, e + 3); if (kk < prev && kk > best) best = kk;
            }
#pragma unroll
            for (int o = 16; o > 0; o >>= 1) {
                unsigned long long ot = __shfl_xor_sync(0xFFFFFFFFu, best, o);
                if (ot > best) best = ot;
            }
            if ((tid & 31) == 0) s->wred[tid >> 5] = best;
            __syncthreads();
            if (tid == 0) {
                unsigned long long bb = s->wred[0];
                for (int i = 1; i < 8; i++) if (s->wred[i] > bb) bb = s->wred[i];
                s->buf[r] = bb;
            }
            __syncthreads();
            prev = s->buf[r];
        }
        cnt = KTOP;
    }

    // ---- Final bitonic sort (descending) of candidates, pad with 0 keys ----
    int n2 = 32;
    while (n2 < cnt) n2 <<= 1;
    for (int i = cnt + tid; i < n2; i += NTHREADS) s->buf[i] = 0ull;
    __syncthreads();
    for (int k = 2; k <= n2; k <<= 1) {
        for (int j = k >> 1; j > 0; j >>= 1) {
            for (int i = tid; i < n2; i += NTHREADS) {
                int l = i ^ j;
                if (l > i) {
                    unsigned long long a = s->buf[i], b = s->buf[l];
                    if ((a < b) == ((i & k) == 0)) {
                        s->buf[i] = b;
                        s->buf[l] = a;
                    }
                }
            }
            __syncthreads();
        }
    }
}

__global__ __launch_bounds__(NTHREADS)
void topk_loss_kernel(const float* __restrict__ logits,
                      const float* __restrict__ targets, int B) {
    __shared__ SMem s;
    const int row = blockIdx.x;
    const int tid = threadIdx.x;
    const size_t off = (size_t)row * CCOLS;

    // Phase A: top-30 indices of targets row
    topk_select((const float4*)(targets + off), &s);
    if (tid < KTOP) s.tIdx[tid] = (int)(~(unsigned)s.buf[tid]);
    __syncthreads();

    // Phase B: top-30 indices of logits row
    topk_select((const float4*)(logits + off), &s);

    if (tid == 0) { s.ov = 0; s.loss = 0.0f; }
    __syncthreads();

    if (tid < KTOP) {
        int my = s.tIdx[tid];
        int c = 0;
#pragma unroll
        for (int i = 0; i < KTOP; i++)
            c += (my == (int)(~(unsigned)s.buf[i]));
        float x = __ldg(&logits[off + (size_t)my]);   // gather; L2-hot
        float p = 1.0f / (1.0f + expf(-x));
        float li = -logf(p + 1e-7f);
        atomicAdd(&s.ov, c);
        atomicAdd(&s.loss, li);
    }
    __syncthreads();
    if (tid == 0) {
        float lm = s.loss * (1.0f / KTOP);
        float w = 1.0f - (float)s.ov * (1.0f / KTOP);
        g_rowloss[row] = lm * w;
    }
}

__global__ void reduce_mean_kernel(float* __restrict__ out, int B) {
    __shared__ float red[8];
    float sum = 0.0f;
    for (int i = threadIdx.x; i < B; i += 256) sum += g_rowloss[i];
#pragma unroll
    for (int o = 16; o > 0; o >>= 1)
        sum += __shfl_xor_sync(0xFFFFFFFFu, sum, o);
    if ((threadIdx.x & 31) == 0) red[threadIdx.x >> 5] = sum;
    __syncthreads();
    if (threadIdx.x == 0) {
        float t = 0.0f;
#pragma unroll
        for (int i = 0; i < 8; i++) t += red[i];
        out[0] = t / (float)B;
    }
}

extern "C" void kernel_launch(void* const* d_in, const int* in_sizes, int n_in,
                              void* d_out, int out_size) {
    const float* logits  = (const float*)d_in[0];
    const float* targets = (const float*)d_in[1];
    int B = in_sizes[0] / CCOLS;
    if (B > MAXB) B = MAXB;
    topk_loss_kernel<<<B, NTHREADS>>>(logits, targets, B);
    reduce_mean_kernel<<<1, 256>>>((float*)d_out, B);
}

// round 10
// speedup vs baseline: 1.2224x; 1.2224x over previous
#include <cuda_runtime.h>
#include <cstdint>

#define NTHREADS 256
#define KTOP 30
#define CCOLS 32000
#define NF4 8000          // float4 per row
#define BOOT4 2048        // float4 in bootstrap chunk (8192 floats)
#define CAP 1024
#define MAXB 4096

__device__ float g_rowloss[MAXB];
__device__ unsigned g_done = 0;

__device__ __forceinline__ unsigned ordu(float f) {
    unsigned u = __float_as_uint(f);
    return (u & 0x80000000u) ? ~u : (u | 0x80000000u);
}
// key: order-preserving float in high bits, ~index low => unique keys,
// equal values break ties toward smaller index (matches jax top_k).
__device__ __forceinline__ unsigned long long mkkey(float f, unsigned idx) {
    return (((unsigned long long)ordu(f)) << 32) | (unsigned long long)(~idx);
}

struct SMem {
    unsigned long long buf[CAP];
    unsigned long long wred[8];
    float gmax[64];
    int   tIdx[KTOP];
    int   lIdx[KTOP];
    float th;
    int   cnt;
    int   isLast;
};

// Exact top-30 index set of one row. On return (synced): outIdx[0..29] filled
// (rank order, but callers only treat it as a set).
__device__ void topk_select(const float4* __restrict__ row4, SMem* s, int* outIdx) {
    const int tid = threadIdx.x;
    if (tid == 0) s->cnt = 0;

    // ---- Bootstrap: load first 8192 elems into regs, derive safe threshold ----
    float4 w[8];
    float m = -3.402823466e38f;
#pragma unroll
    for (int k = 0; k < 8; k++) {
        w[k] = __ldg(&row4[tid + (k << 8)]);
        m = fmaxf(m, fmaxf(fmaxf(w[k].x, w[k].y), fmaxf(w[k].z, w[k].w)));
    }
    m = fmaxf(m, __shfl_xor_sync(0xFFFFFFFFu, m, 1));
    m = fmaxf(m, __shfl_xor_sync(0xFFFFFFFFu, m, 2));
    if ((tid & 3) == 0) s->gmax[tid >> 2] = m;
    __syncthreads();

    // 30th-largest of 64 group maxes by rank counting (no sort).
    if (tid < 64) {
        float v = s->gmax[tid];
        int r = 0;
#pragma unroll 8
        for (int j = 0; j < 64; j++) {
            float o = s->gmax[j];
            r += (o > v) || (o == v && j < tid);
        }
        if (r == KTOP - 1) s->th = v;   // th <= 30th-largest element of the row
    }
    __syncthreads();
    const float th = s->th;

    // ---- Filter bootstrap chunk from registers (no re-read) ----
#pragma unroll
    for (int k = 0; k < 8; k++) {
        unsigned e = (unsigned)((tid + (k << 8)) << 2);
        float4 v = w[k];
        if (v.x >= th) { int p = atomicAdd(&s->cnt, 1); if (p < CAP) s->buf[p] = mkkey(v.x, e); }
        if (v.y >= th) { int p = atomicAdd(&s->cnt, 1); if (p < CAP) s->buf[p] = mkkey(v.y, e + 1); }
        if (v.z >= th) { int p = atomicAdd(&s->cnt, 1); if (p < CAP) s->buf[p] = mkkey(v.z, e + 2); }
        if (v.w >= th) { int p = atomicAdd(&s->cnt, 1); if (p < CAP) s->buf[p] = mkkey(v.w, e + 3); }
    }

    // ---- Stream the remaining 23808 elems once ----
    const float qnan = __int_as_float(0x7fc00000);
    for (int base = BOOT4; base < NF4; base += NTHREADS * 8) {
        float4 u[8];
#pragma unroll
        for (int k = 0; k < 8; k++) {
            int j4 = base + (k << 8) + tid;
            u[k] = (j4 < NF4) ? __ldg(&row4[j4])
                              : make_float4(qnan, qnan, qnan, qnan);
        }
#pragma unroll
        for (int k = 0; k < 8; k++) {
            int j4 = base + (k << 8) + tid;
            unsigned e = (unsigned)(j4 << 2);
            float4 v = u[k];
            if (v.x >= th) { int p = atomicAdd(&s->cnt, 1); if (p < CAP) s->buf[p] = mkkey(v.x, e); }
            if (v.y >= th) { int p = atomicAdd(&s->cnt, 1); if (p < CAP) s->buf[p] = mkkey(v.y, e + 1); }
            if (v.z >= th) { int p = atomicAdd(&s->cnt, 1); if (p < CAP) s->buf[p] = mkkey(v.z, e + 2); }
            if (v.w >= th) { int p = atomicAdd(&s->cnt, 1); if (p < CAP) s->buf[p] = mkkey(v.w, e + 3); }
        }
    }
    __syncthreads();
    int cnt = s->cnt;

    // ---- Fallback (statistically never taken): exact 30x argmax ----
    if (cnt > CAP) {
        unsigned long long prev = 0xFFFFFFFFFFFFFFFFull;
        for (int r = 0; r < KTOP; r++) {
            unsigned long long best = 0ull;
            for (int j4 = tid; j4 < NF4; j4 += NTHREADS) {
                float4 v = __ldg(&row4[j4]);
                unsigned e = (unsigned)(j4 << 2);
                unsigned long long kk;
                kk = mkkey(v.x, e);     if (kk < prev && kk > best) best = kk;
                kk = mkkey(v.y, e + 1); if (kk < prev && kk > best) best = kk;
                kk = mkkey(v.z, e + 2); if (kk < prev && kk > best) best = kk;
                kk = mkkey(v.w, e + 3); if (kk < prev && kk > best) best = kk;
            }
#pragma unroll
            for (int o = 16; o > 0; o >>= 1) {
                unsigned long long ot = __shfl_xor_sync(0xFFFFFFFFu, best, o);
                if (ot > best) best = ot;
            }
            if ((tid & 31) == 0) s->wred[tid >> 5] = best;
            __syncthreads();
            if (tid == 0) {
                unsigned long long bb = s->wred[0];
                for (int i = 1; i < 8; i++) if (s->wred[i] > bb) bb = s->wred[i];
                s->buf[r] = bb;
            }
            __syncthreads();
            prev = s->buf[r];
        }
        cnt = KTOP;
    }

    // ---- Exact top-30 set by rank counting (keys unique; no sort) ----
    for (int i = tid; i < cnt; i += NTHREADS) {
        unsigned long long key = s->buf[i];
        int r = 0;
        for (int j = 0; j < cnt; j++) r += (s->buf[j] > key);
        if (r < KTOP) outIdx[r] = (int)(~(unsigned)key);
    }
    __syncthreads();
}

__global__ __launch_bounds__(NTHREADS)
void topk_loss_kernel(const float* __restrict__ logits,
                      const float* __restrict__ targets,
                      int B, float* __restrict__ out) {
    __shared__ SMem s;
    const int row = blockIdx.x;
    const int tid = threadIdx.x;
    const size_t off = (size_t)row * CCOLS;

    topk_select((const float4*)(targets + off), &s, s.tIdx);
    topk_select((const float4*)(logits + off),  &s, s.lIdx);

    // threads 0..29 live in warp 0 -> deterministic shfl reductions
    if (tid < 32) {
        float li = 0.0f;
        int   c  = 0;
        if (tid < KTOP) {
            int my = s.tIdx[tid];
#pragma unroll
            for (int i = 0; i < KTOP; i++) c += (my == s.lIdx[i]);
            float x = __ldg(&logits[off + (size_t)my]);   // L2-hot gather
            float p = 1.0f / (1.0f + expf(-x));
            li = -logf(p + 1e-7f);
        }
#pragma unroll
        for (int o = 16; o > 0; o >>= 1) {
            li += __shfl_xor_sync(0xFFFFFFFFu, li, o);
            c  += __shfl_xor_sync(0xFFFFFFFFu, c,  o);
        }
        if (tid == 0) {
            float lm = li * (1.0f / KTOP);
            float w  = 1.0f - (float)c * (1.0f / KTOP);
            g_rowloss[row] = lm * w;
        }
    }

    // ---- last CTA performs deterministic ordered mean ----
    if (tid == 0) {
        unsigned t;
        // release: all prior writes (g_rowloss[row]) visible before ticket.
        asm volatile("atom.add.release.gpu.u32 %0, [%1], 1;"
                     : "=r"(t) : "l"(&g_done) : "memory");
        s.isLast = (t == (unsigned)(gridDim.x - 1));
    }
    __syncthreads();
    if (s.isLast) {
        // acquire: see all CTAs' g_rowloss writes.
        if (tid == 0) {
            unsigned dummy;
            asm volatile("atom.exch.acquire.gpu.b32 %0, [%1], 0;"
                         : "=r"(dummy) : "l"(&g_done) : "memory");  // also resets
        }
        __syncthreads();
        float sum = 0.0f;
        for (int i = tid; i < B; i += NTHREADS) sum += g_rowloss[i];
#pragma unroll
        for (int o = 16; o > 0; o >>= 1)
            sum += __shfl_xor_sync(0xFFFFFFFFu, sum, o);
        __shared__ float red[8];
        if ((tid & 31) == 0) red[tid >> 5] = sum;
        __syncthreads();
        if (tid == 0) {
            float t2 = 0.0f;
#pragma unroll
            for (int i = 0; i < 8; i++) t2 += red[i];
            out[0] = t2 / (float)B;
        }
    }
}

extern "C" void kernel_launch(void* const* d_in, const int* in_sizes, int n_in,
                              void* d_out, int out_size) {
    const float* logits  = (const float*)d_in[0];
    const float* targets = (const float*)d_in[1];
    int B = in_sizes[0] / CCOLS;
    if (B > MAXB) B = MAXB;
    topk_loss_kernel<<<B, NTHREADS>>>(logits, targets, B, (float*)d_out);
}